// round 14
// baseline (speedup 1.0000x reference)
#include <cuda_runtime.h>
#include <cuda_fp16.h>
#include <math.h>

#define NN 50000
#define EE 1600000
#define ETOT (EE + NN)
#define G64BLK ((NN + 127) / 128)
#define EBLK ((ETOT + 255) / 256)

// ---------------- scratch ----------------
__device__ uint4  g_h16v[NN * 8];    // fp16 h, 16B-aligned (64 halves per node)
__device__ float  g_x2[NN * 64];
__device__ float  g_als[NN * 4];
__device__ float  g_ald[NN * 4];
__device__ float  g_acc[NN * 16];
__device__ int    g_deg[NN];
__device__ int    g_off[NN + 1];
__device__ int    g_cur[NN];
__device__ int    g_csr[ETOT];

// ================= CSR build =================
__global__ void hist_kernel(const int* __restrict__ ei) {
    int e = blockIdx.x * blockDim.x + threadIdx.x;
    if (e >= ETOT) return;
    int d = (e < EE) ? ei[EE + e] : (e - EE);
    atomicAdd(&g_deg[d], 1);
}

// scan also RE-ZEROES g_deg after use, so no memset launch is needed per replay
// (g_deg is static-zero on the very first call; invariant maintained thereafter).
__global__ void scan_kernel() {
    __shared__ int partial[1024];
    int t = threadIdx.x;
    const int C = (NN + 1023) / 1024;
    int b0 = t * C;
    int b1 = min(b0 + C, NN);
    int sum = 0;
    for (int i = b0; i < b1; i++) sum += g_deg[i];
    partial[t] = sum;
    __syncthreads();
    for (int off = 1; off < 1024; off <<= 1) {
        int v = (t >= off) ? partial[t - off] : 0;
        __syncthreads();
        partial[t] += v;
        __syncthreads();
    }
    int run = (t == 0) ? 0 : partial[t - 1];
    for (int i = b0; i < b1; i++) {
        g_off[i] = run;
        g_cur[i] = run;
        run += g_deg[i];
        g_deg[i] = 0;
    }
    if (t == 1023) g_off[NN] = run;
}

// ===== fused: layer-1 GEMM (blocks [0, G64BLK)) || CSR scatter (rest) =====
__global__ void __launch_bounds__(256)
fused_gemm1_scatter(const float* __restrict__ X, const float* __restrict__ W,
                    const float* __restrict__ a_s, const float* __restrict__ a_d,
                    const int* __restrict__ ei) {
    constexpr int IN = 128;
    constexpr int KT = 32;
    constexpr int SXS = 132;
    __shared__ float sW[KT][64];
    __shared__ float sX2[KT][SXS];
    int t = threadIdx.x;

    if (blockIdx.x >= G64BLK) {
        int e = (blockIdx.x - G64BLK) * 256 + t;
        if (e < ETOT) {
            int s, d;
            if (e < EE) { s = ei[e]; d = ei[EE + e]; } else { s = e - EE; d = s; }
            int pos = atomicAdd(&g_cur[d], 1);
            g_csr[pos] = s;
        }
        return;
    }

    int tx = t & 15, ty = t >> 4;
    int row0 = blockIdx.x * 128;
    float acc[8][4];
#pragma unroll
    for (int r = 0; r < 8; r++)
#pragma unroll
        for (int c = 0; c < 4; c++) acc[r][c] = 0.f;

    for (int kt = 0; kt < IN; kt += KT) {
#pragma unroll
        for (int i = t; i < KT * 16; i += 256) {
            int kk = i >> 4;
            int c4 = (i & 15) << 2;
            *(float4*)&sW[kk][c4] = *(const float4*)&W[(kt + kk) * 64 + c4];
        }
#pragma unroll
        for (int i = t; i < 128 * (KT / 4); i += 256) {
            int r = i >> 3;
            int k4 = (i & 7) << 2;
            int gr = row0 + r;
            float4 v = (gr < NN) ? *(const float4*)&X[gr * IN + kt + k4]
                                 : make_float4(0.f, 0.f, 0.f, 0.f);
            sX2[k4 + 0][r] = v.x;
            sX2[k4 + 1][r] = v.y;
            sX2[k4 + 2][r] = v.z;
            sX2[k4 + 3][r] = v.w;
        }
        __syncthreads();
#pragma unroll
        for (int k = 0; k < KT; k++) {
            float4 w4 = *(float4*)&sW[k][tx * 4];
            float4 xa = *(float4*)&sX2[k][ty * 8];
            float4 xb = *(float4*)&sX2[k][ty * 8 + 4];
            float xr[8] = {xa.x, xa.y, xa.z, xa.w, xb.x, xb.y, xb.z, xb.w};
#pragma unroll
            for (int r = 0; r < 8; r++) {
                acc[r][0] += xr[r] * w4.x;
                acc[r][1] += xr[r] * w4.y;
                acc[r][2] += xr[r] * w4.z;
                acc[r][3] += xr[r] * w4.w;
            }
        }
        __syncthreads();
    }

    int h = tx >> 2;
    float4 asv = *(const float4*)&a_s[h * 16 + (tx & 3) * 4];
    float4 adv = *(const float4*)&a_d[h * 16 + (tx & 3) * 4];
    __half2* h2out = (__half2*)g_h16v;
#pragma unroll
    for (int r = 0; r < 8; r++) {
        int gr = row0 + ty * 8 + r;
        float ps = acc[r][0] * asv.x + acc[r][1] * asv.y + acc[r][2] * asv.z + acc[r][3] * asv.w;
        float pd = acc[r][0] * adv.x + acc[r][1] * adv.y + acc[r][2] * adv.z + acc[r][3] * adv.w;
        ps += __shfl_xor_sync(0xffffffffu, ps, 1);
        ps += __shfl_xor_sync(0xffffffffu, ps, 2);
        pd += __shfl_xor_sync(0xffffffffu, pd, 1);
        pd += __shfl_xor_sync(0xffffffffu, pd, 2);
        if (gr < NN) {
            h2out[(gr * 64 + tx * 4) >> 1] = __floats2half2_rn(acc[r][0], acc[r][1]);
            h2out[((gr * 64 + tx * 4) >> 1) + 1] = __floats2half2_rn(acc[r][2], acc[r][3]);
            if ((tx & 3) == 0) {
                g_als[gr * 4 + h] = ps;
                g_ald[gr * 4 + h] = pd;
            }
        }
    }
}

// ------- GEMM 64-wide (layer 2), 128-row tile, fused al + fp16 out ----
template <int IN>
__global__ void __launch_bounds__(256)
gemm64(const float* __restrict__ X, const float* __restrict__ W,
       const float* __restrict__ a_s, const float* __restrict__ a_d) {
    constexpr int KT = 32;
    constexpr int SXS = 132;
    __shared__ float sW[KT][64];
    __shared__ float sX2[KT][SXS];
    int t = threadIdx.x;
    int tx = t & 15, ty = t >> 4;
    int row0 = blockIdx.x * 128;
    float acc[8][4];
#pragma unroll
    for (int r = 0; r < 8; r++)
#pragma unroll
        for (int c = 0; c < 4; c++) acc[r][c] = 0.f;

    for (int kt = 0; kt < IN; kt += KT) {
#pragma unroll
        for (int i = t; i < KT * 16; i += 256) {
            int kk = i >> 4;
            int c4 = (i & 15) << 2;
            *(float4*)&sW[kk][c4] = *(const float4*)&W[(kt + kk) * 64 + c4];
        }
#pragma unroll
        for (int i = t; i < 128 * (KT / 4); i += 256) {
            int r = i >> 3;
            int k4 = (i & 7) << 2;
            int gr = row0 + r;
            float4 v = (gr < NN) ? *(const float4*)&X[gr * IN + kt + k4]
                                 : make_float4(0.f, 0.f, 0.f, 0.f);
            sX2[k4 + 0][r] = v.x;
            sX2[k4 + 1][r] = v.y;
            sX2[k4 + 2][r] = v.z;
            sX2[k4 + 3][r] = v.w;
        }
        __syncthreads();
#pragma unroll
        for (int k = 0; k < KT; k++) {
            float4 w4 = *(float4*)&sW[k][tx * 4];
            float4 xa = *(float4*)&sX2[k][ty * 8];
            float4 xb = *(float4*)&sX2[k][ty * 8 + 4];
            float xr[8] = {xa.x, xa.y, xa.z, xa.w, xb.x, xb.y, xb.z, xb.w};
#pragma unroll
            for (int r = 0; r < 8; r++) {
                acc[r][0] += xr[r] * w4.x;
                acc[r][1] += xr[r] * w4.y;
                acc[r][2] += xr[r] * w4.z;
                acc[r][3] += xr[r] * w4.w;
            }
        }
        __syncthreads();
    }

    int h = tx >> 2;
    float4 asv = *(const float4*)&a_s[h * 16 + (tx & 3) * 4];
    float4 adv = *(const float4*)&a_d[h * 16 + (tx & 3) * 4];
    __half2* h2out = (__half2*)g_h16v;
#pragma unroll
    for (int r = 0; r < 8; r++) {
        int gr = row0 + ty * 8 + r;
        float ps = acc[r][0] * asv.x + acc[r][1] * asv.y + acc[r][2] * asv.z + acc[r][3] * asv.w;
        float pd = acc[r][0] * adv.x + acc[r][1] * adv.y + acc[r][2] * adv.z + acc[r][3] * adv.w;
        ps += __shfl_xor_sync(0xffffffffu, ps, 1);
        ps += __shfl_xor_sync(0xffffffffu, ps, 2);
        pd += __shfl_xor_sync(0xffffffffu, pd, 1);
        pd += __shfl_xor_sync(0xffffffffu, pd, 2);
        if (gr < NN) {
            h2out[(gr * 64 + tx * 4) >> 1] = __floats2half2_rn(acc[r][0], acc[r][1]);
            h2out[((gr * 64 + tx * 4) >> 1) + 1] = __floats2half2_rn(acc[r][2], acc[r][3]);
            if ((tx & 3) == 0) {
                g_als[gr * 4 + h] = ps;
                g_ald[gr * 4 + h] = pd;
            }
        }
    }
}

// ------- GEMM layer 3 (64->16): fused al epilogue, fp16-only output -------
__global__ void gemm16(const float* __restrict__ X, const float* __restrict__ W,
                       const float* __restrict__ a_s, const float* __restrict__ a_d) {
    constexpr int IN = 64, OUT = 16;
    constexpr int RB = 64;
    __shared__ float sW[IN * OUT];
    __shared__ float sX[RB * IN];
    int t = threadIdx.x;
    int tx = t & 15, ty = t >> 4;
    int row0 = blockIdx.x * RB;

    for (int i = t; i < IN * OUT; i += 256) sW[i] = W[i];
    for (int i = t; i < RB * IN; i += 256) {
        int r = row0 + i / IN;
        sX[i] = (r < NN) ? X[r * IN + (i % IN)] : 0.f;
    }
    __syncthreads();

    float acc[4];
#pragma unroll
    for (int rr = 0; rr < 4; rr++) acc[rr] = 0.f;
    const float* xs = &sX[ty * 4 * IN];
    for (int k = 0; k < IN; k++) {
        float wv = sW[k * OUT + tx];
#pragma unroll
        for (int rr = 0; rr < 4; rr++) acc[rr] += xs[rr * IN + k] * wv;
    }
    float asx = __ldg(&a_s[tx]), adx = __ldg(&a_d[tx]);
    __half* h16 = (__half*)g_h16v;
#pragma unroll
    for (int rr = 0; rr < 4; rr++) {
        int r = row0 + ty * 4 + rr;
        float ps = acc[rr] * asx;
        float pd = acc[rr] * adx;
#pragma unroll
        for (int off = 1; off < 16; off <<= 1) {
            ps += __shfl_xor_sync(0xffffffffu, ps, off);
            pd += __shfl_xor_sync(0xffffffffu, pd, off);
        }
        if (r < NN) {
            h16[r * OUT + tx] = __float2half_rn(acc[rr]);
            if (tx == 0) {
                g_als[r] = ps;
                g_ald[r] = pd;
            }
        }
    }
}

__device__ __forceinline__ float lrelu_exp(float v) {
    v = (v > 0.f) ? v : 0.2f * v;
    return __expf(v);
}

// ============ fused gather-aggregation, 64-wide (layers 1 & 2) ============
// TWO nodes per warp with pipelined startup: off/ald/csr/als for both nodes
// issued in the prologue; node 1's first batch is already in registers while
// node 0 is processed. Inner structure identical to R13 (proven shape).
__global__ void __launch_bounds__(256)
agg64(const float* __restrict__ b,
      const float* __restrict__ gg, const float* __restrict__ bb,
      const float* __restrict__ mm, const float* __restrict__ vv,
      float* __restrict__ xnext) {
    __shared__ float2 sh_sex[8][4][34];
    int w = threadIdx.x >> 5;
    int lane = threadIdx.x & 31;
    int gw = (blockIdx.x * blockDim.x + threadIdx.x) >> 5;
    int n0 = gw * 2;
    if (n0 >= NN) return;
    int n1 = n0 + 1;                     // NN even -> always valid
    int eg = lane >> 4;                  // edge half 0/1
    int cq = lane & 15;                  // col quad: cols 4*cq .. 4*cq+3
    int h = cq >> 2;                     // head of those cols
    const uint2* pu2 = (const uint2*)g_h16v;

    // ---- pipelined prologue: both nodes' metadata + first-batch csr/als ----
    int beg0 = __ldg(&g_off[n0]);
    int end0 = __ldg(&g_off[n0 + 1]);
    int end1 = __ldg(&g_off[n1 + 1]);
    int beg1 = end0;
    float4 ad40 = __ldg((const float4*)&g_ald[n0 * 4]);
    float4 ad41 = __ldg((const float4*)&g_ald[n1 * 4]);
    int i0 = beg0 + lane;
    bool v0 = i0 < end0;
    int s0 = v0 ? __ldg(&g_csr[i0]) : 0;
    int i1 = beg1 + lane;
    bool v1 = i1 < end1;
    int s1 = v1 ? __ldg(&g_csr[i1]) : 0;
    float4 as40 = __ldg((const float4*)&g_als[s0 * 4]);
    float4 as41 = __ldg((const float4*)&g_als[s1 * 4]);

#pragma unroll 1
    for (int node = 0; node < 2; node++) {
        int n = node ? n1 : n0;
        int beg = node ? beg1 : beg0;
        int end = node ? end1 : end0;
        float4 ad4 = node ? ad41 : ad40;
        float a0 = 0.f, a1 = 0.f, a2 = 0.f, a3 = 0.f, dn = 0.f;
        for (int base = beg; base < end; base += 32) {
            int s;
            float4 as4;
            bool valid;
            if (base == beg) {
                s = node ? s1 : s0;
                as4 = node ? as41 : as40;
                valid = node ? v1 : v0;
            } else {
                int idx = base + lane;
                valid = idx < end;
                s = valid ? __ldg(&g_csr[idx]) : 0;
                as4 = __ldg((const float4*)&g_als[s * 4]);
            }
            float sf = __int_as_float(s * 16);   // row base in uint2 units
            float e0 = valid ? lrelu_exp(as4.x + ad4.x) : 0.f;
            float e1 = valid ? lrelu_exp(as4.y + ad4.y) : 0.f;
            float e2 = valid ? lrelu_exp(as4.z + ad4.z) : 0.f;
            float e3 = valid ? lrelu_exp(as4.w + ad4.w) : 0.f;
            __syncwarp();
            sh_sex[w][0][lane] = make_float2(sf, e0);
            sh_sex[w][1][lane] = make_float2(sf, e1);
            sh_sex[w][2][lane] = make_float2(sf, e2);
            sh_sex[w][3][lane] = make_float2(sf, e3);
            __syncwarp();
            int nk8 = (min(32, end - base) + 7) & ~7;
            for (int j0 = 0; j0 < nk8; j0 += 8) {
#pragma unroll
                for (int u = 0; u < 4; u++) {
                    int j = j0 + 2 * u + eg;
                    float2 p = sh_sex[w][h][j];
                    int sj16 = __float_as_int(p.x);
                    float ex = p.y;
                    uint2 v = __ldg(&pu2[sj16 + cq]);
                    float2 f0 = __half22float2(*(__half2*)&v.x);
                    float2 f1 = __half22float2(*(__half2*)&v.y);
                    a0 += ex * f0.x;
                    a1 += ex * f0.y;
                    a2 += ex * f1.x;
                    a3 += ex * f1.y;
                    dn += ex;
                }
            }
        }
        a0 += __shfl_xor_sync(0xffffffffu, a0, 16);
        a1 += __shfl_xor_sync(0xffffffffu, a1, 16);
        a2 += __shfl_xor_sync(0xffffffffu, a2, 16);
        a3 += __shfl_xor_sync(0xffffffffu, a3, 16);
        dn += __shfl_xor_sync(0xffffffffu, dn, 16);
        if (lane < 16) {
            float inv = 1.f / (dn + 1e-16f);
            int c0 = 4 * cq;
            float a[4] = {a0 * inv, a1 * inv, a2 * inv, a3 * inv};
            float o[4];
#pragma unroll
            for (int i = 0; i < 4; i++) {
                int col = c0 + i;
                float y = (a[i] + __ldg(&b[col]) - __ldg(&mm[col])) *
                              rsqrtf(__ldg(&vv[col]) + 1e-5f) * __ldg(&gg[col]) +
                          __ldg(&bb[col]);
                o[i] = fmaxf(y, 0.f);
            }
            *(float4*)&xnext[n * 64 + c0] = make_float4(o[0], o[1], o[2], o[3]);
        }
    }
}

// ============ fused gather-aggregation, 16-wide (layer 3) ============
// TWO nodes per warp with pipelined startup, same principle as agg64.
// 8 edge-groups of 4 lanes; lane owns 4 cols via uint2.
__global__ void __launch_bounds__(256)
agg16() {
    __shared__ float2 sh_sex[8][33];
    int w = threadIdx.x >> 5;
    int lane = threadIdx.x & 31;
    int gw = (blockIdx.x * blockDim.x + threadIdx.x) >> 5;
    int n0 = gw * 2;
    if (n0 >= NN) return;
    int n1 = n0 + 1;
    int q = lane >> 2;        // edge-group 0..7
    int cg = lane & 3;        // uint2 col group: cols 4*cg .. 4*cg+3
    const uint2* pu2 = (const uint2*)g_h16v;   // row = 16 halves = 4 uint2

    int beg0 = __ldg(&g_off[n0]);
    int end0 = __ldg(&g_off[n0 + 1]);
    int end1 = __ldg(&g_off[n1 + 1]);
    int beg1 = end0;
    float ad0 = __ldg(&g_ald[n0]);
    float ad1 = __ldg(&g_ald[n1]);
    int i0 = beg0 + lane;
    bool v0 = i0 < end0;
    int s0 = v0 ? __ldg(&g_csr[i0]) : 0;
    int i1 = beg1 + lane;
    bool v1 = i1 < end1;
    int s1 = v1 ? __ldg(&g_csr[i1]) : 0;
    float al0 = __ldg(&g_als[s0]);
    float al1 = __ldg(&g_als[s1]);

#pragma unroll 1
    for (int node = 0; node < 2; node++) {
        int n = node ? n1 : n0;
        int beg = node ? beg1 : beg0;
        int end = node ? end1 : end0;
        float ad = node ? ad1 : ad0;
        float a0 = 0.f, a1 = 0.f, a2 = 0.f, a3 = 0.f, dn = 0.f;
        for (int base = beg; base < end; base += 32) {
            int s;
            float al;
            bool valid;
            if (base == beg) {
                s = node ? s1 : s0;
                al = node ? al1 : al0;
                valid = node ? v1 : v0;
            } else {
                int idx = base + lane;
                valid = idx < end;
                s = valid ? __ldg(&g_csr[idx]) : 0;
                al = __ldg(&g_als[s]);
            }
            float ex = valid ? lrelu_exp(al + ad) : 0.f;
            __syncwarp();
            sh_sex[w][lane] = make_float2(__int_as_float(s * 4), ex);
            __syncwarp();
            int nk8 = (min(32, end - base) + 7) & ~7;
            for (int j0 = 0; j0 < nk8; j0 += 8) {
                int j = j0 + q;
                float2 p = sh_sex[w][j];
                int sj4 = __float_as_int(p.x);
                float exj = p.y;
                uint2 v = __ldg(&pu2[sj4 + cg]);
                float2 f0 = __half22float2(*(__half2*)&v.x);
                float2 f1 = __half22float2(*(__half2*)&v.y);
                a0 += exj * f0.x;
                a1 += exj * f0.y;
                a2 += exj * f1.x;
                a3 += exj * f1.y;
                dn += exj;
            }
        }
#pragma unroll
        for (int off = 4; off <= 16; off <<= 1) {
            a0 += __shfl_xor_sync(0xffffffffu, a0, off);
            a1 += __shfl_xor_sync(0xffffffffu, a1, off);
            a2 += __shfl_xor_sync(0xffffffffu, a2, off);
            a3 += __shfl_xor_sync(0xffffffffu, a3, off);
            dn += __shfl_xor_sync(0xffffffffu, dn, off);
        }
        if (lane < 4) {
            float inv = 1.f / (dn + 1e-16f);
            float4 o = make_float4(a0 * inv, a1 * inv, a2 * inv, a3 * inv);
            *(float4*)&g_acc[n * 16 + 4 * cg] = o;
        }
    }
}

// ---------------- epilogue layer 3 ----------------
__global__ void ep3(const float* __restrict__ b3, const float* __restrict__ gg,
                    const float* __restrict__ bb, const float* __restrict__ mm,
                    const float* __restrict__ vv, const float* __restrict__ fw1,
                    const float* __restrict__ fb1, const float* __restrict__ fw2,
                    const float* __restrict__ fb2, float* __restrict__ out) {
    int n = blockIdx.x * blockDim.x + threadIdx.x;
    if (n >= NN) return;
    float t[16];
#pragma unroll
    for (int c = 0; c < 16; c++) {
        float y = (g_acc[n * 16 + c] + __ldg(&b3[c]) - __ldg(&mm[c])) *
                      rsqrtf(__ldg(&vv[c]) + 1e-5f) * __ldg(&gg[c]) +
                  __ldg(&bb[c]);
        t[c] = fmaxf(y, 0.f);
    }
    float o = __ldg(&fb2[0]);
#pragma unroll
    for (int oo = 0; oo < 8; oo++) {
        float z = __ldg(&fb1[oo]);
#pragma unroll
        for (int c = 0; c < 16; c++) z += t[c] * __ldg(&fw1[c * 8 + oo]);
        z = fmaxf(z, 0.f);
        o += z * __ldg(&fw2[oo]);
    }
    out[n] = o;
}

// ---------------- launch ----------------
extern "C" void kernel_launch(void* const* d_in, const int* in_sizes, int n_in,
                              void* d_out, int out_size) {
    const float* x = (const float*)d_in[0];
    const int* ei = (const int*)d_in[1];
    const float* W1 = (const float*)d_in[2];
    const float* as1 = (const float*)d_in[3];
    const float* ad1 = (const float*)d_in[4];
    const float* b1 = (const float*)d_in[5];
    const float* g1 = (const float*)d_in[6];
    const float* bb1 = (const float*)d_in[7];
    const float* m1 = (const float*)d_in[8];
    const float* v1 = (const float*)d_in[9];
    const float* W2 = (const float*)d_in[10];
    const float* as2 = (const float*)d_in[11];
    const float* ad2 = (const float*)d_in[12];
    const float* b2 = (const float*)d_in[13];
    const float* g2 = (const float*)d_in[14];
    const float* bb2 = (const float*)d_in[15];
    const float* m2 = (const float*)d_in[16];
    const float* v2 = (const float*)d_in[17];
    const float* W3 = (const float*)d_in[18];
    const float* as3 = (const float*)d_in[19];
    const float* ad3 = (const float*)d_in[20];
    const float* b3 = (const float*)d_in[21];
    const float* g3 = (const float*)d_in[22];
    const float* bb3 = (const float*)d_in[23];
    const float* m3 = (const float*)d_in[24];
    const float* v3 = (const float*)d_in[25];
    const float* fw1 = (const float*)d_in[26];
    const float* fb1 = (const float*)d_in[27];
    const float* fw2 = (const float*)d_in[28];
    const float* fb2 = (const float*)d_in[29];
    float* out = (float*)d_out;

    float* px2 = nullptr;
    cudaGetSymbolAddress((void**)&px2, g_x2);

    const int TB = 256;
    int nblk = (NN + TB - 1) / TB;
    int aggblk = (NN / 2 * 32 + TB - 1) / TB;   // 2 nodes per warp

    // ---- CSR: hist + scan (scan re-zeroes deg), scatter fused with L1 GEMM ----
    hist_kernel<<<EBLK, TB>>>(ei);
    scan_kernel<<<1, 1024>>>();

    // ---- Layer 1 GEMM || CSR scatter ----
    fused_gemm1_scatter<<<G64BLK + EBLK, TB>>>(x, W1, as1, ad1, ei);
    agg64<<<aggblk, TB>>>(b1, g1, bb1, m1, v1, px2);

    // ---- Layer 2 ----
    gemm64<64><<<G64BLK, TB>>>(px2, W2, as2, ad2);
    agg64<<<aggblk, TB>>>(b2, g2, bb2, m2, v2, px2);

    // ---- Layer 3 ----
    gemm16<<<(NN + 63) / 64, TB>>>(px2, W3, as3, ad3);
    agg16<<<aggblk, TB>>>();
    ep3<<<nblk, TB>>>(b3, g3, bb3, m3, v3, fw1, fb1, fw2, fb2, out);
}

// round 15
// speedup vs baseline: 1.6140x; 1.6140x over previous
#include <cuda_runtime.h>
#include <cuda_fp16.h>
#include <math.h>

#define NN 50000
#define EE 1600000
#define ETOT (EE + NN)
#define G64BLK ((NN + 127) / 128)          // 391 gemm1 tiles
#define G64A 196
#define G64B (G64BLK - G64A)               // 195
#define EBLK ((ETOT + 255) / 256)
#define NCHK 196                            // scan chunks of 256 (196*256 >= NN)

// ---------------- scratch ----------------
__device__ uint4  g_h16v[NN * 8];    // fp16 h, 16B-aligned (64 halves per node)
__device__ float  g_x2[NN * 64];
__device__ float  g_als[NN * 4];
__device__ float  g_ald[NN * 4];
__device__ float  g_acc[NN * 16];
__device__ int    g_deg[NN];         // static-zero at start; re-zeroed by scanBC
__device__ int    g_bsum[NCHK];
__device__ int    g_off[NN + 1];
__device__ int    g_cur[NN];
__device__ int    g_csr[ETOT];

// ------------- shared gemm1 tile body (layer 1: 128 -> 64, fused al) --------
__device__ __forceinline__ void gemm1_tile(int tile, const float* __restrict__ X,
                                           const float* __restrict__ W,
                                           const float* __restrict__ a_s,
                                           const float* __restrict__ a_d) {
    constexpr int IN = 128;
    constexpr int KT = 32;
    constexpr int SXS = 132;
    __shared__ float sW[KT][64];
    __shared__ float sX2[KT][SXS];
    int t = threadIdx.x;
    int tx = t & 15, ty = t >> 4;
    int row0 = tile * 128;
    float acc[8][4];
#pragma unroll
    for (int r = 0; r < 8; r++)
#pragma unroll
        for (int c = 0; c < 4; c++) acc[r][c] = 0.f;

    for (int kt = 0; kt < IN; kt += KT) {
#pragma unroll
        for (int i = t; i < KT * 16; i += 256) {
            int kk = i >> 4;
            int c4 = (i & 15) << 2;
            *(float4*)&sW[kk][c4] = *(const float4*)&W[(kt + kk) * 64 + c4];
        }
#pragma unroll
        for (int i = t; i < 128 * (KT / 4); i += 256) {
            int r = i >> 3;
            int k4 = (i & 7) << 2;
            int gr = row0 + r;
            float4 v = (gr < NN) ? *(const float4*)&X[gr * IN + kt + k4]
                                 : make_float4(0.f, 0.f, 0.f, 0.f);
            sX2[k4 + 0][r] = v.x;
            sX2[k4 + 1][r] = v.y;
            sX2[k4 + 2][r] = v.z;
            sX2[k4 + 3][r] = v.w;
        }
        __syncthreads();
#pragma unroll
        for (int k = 0; k < KT; k++) {
            float4 w4 = *(float4*)&sW[k][tx * 4];
            float4 xa = *(float4*)&sX2[k][ty * 8];
            float4 xb = *(float4*)&sX2[k][ty * 8 + 4];
            float xr[8] = {xa.x, xa.y, xa.z, xa.w, xb.x, xb.y, xb.z, xb.w};
#pragma unroll
            for (int r = 0; r < 8; r++) {
                acc[r][0] += xr[r] * w4.x;
                acc[r][1] += xr[r] * w4.y;
                acc[r][2] += xr[r] * w4.z;
                acc[r][3] += xr[r] * w4.w;
            }
        }
        __syncthreads();
    }

    int h = tx >> 2;
    float4 asv = *(const float4*)&a_s[h * 16 + (tx & 3) * 4];
    float4 adv = *(const float4*)&a_d[h * 16 + (tx & 3) * 4];
    __half2* h2out = (__half2*)g_h16v;
#pragma unroll
    for (int r = 0; r < 8; r++) {
        int gr = row0 + ty * 8 + r;
        float ps = acc[r][0] * asv.x + acc[r][1] * asv.y + acc[r][2] * asv.z + acc[r][3] * asv.w;
        float pd = acc[r][0] * adv.x + acc[r][1] * adv.y + acc[r][2] * adv.z + acc[r][3] * adv.w;
        ps += __shfl_xor_sync(0xffffffffu, ps, 1);
        ps += __shfl_xor_sync(0xffffffffu, ps, 2);
        pd += __shfl_xor_sync(0xffffffffu, pd, 1);
        pd += __shfl_xor_sync(0xffffffffu, pd, 2);
        if (gr < NN) {
            h2out[(gr * 64 + tx * 4) >> 1] = __floats2half2_rn(acc[r][0], acc[r][1]);
            h2out[((gr * 64 + tx * 4) >> 1) + 1] = __floats2half2_rn(acc[r][2], acc[r][3]);
            if ((tx & 3) == 0) {
                g_als[gr * 4 + h] = ps;
                g_ald[gr * 4 + h] = pd;
            }
        }
    }
}

// ===== K1: gemm1 tiles [0, G64A) || hist =====
__global__ void __launch_bounds__(256)
k1_gemm1a_hist(const float* __restrict__ X, const float* __restrict__ W,
               const float* __restrict__ a_s, const float* __restrict__ a_d,
               const int* __restrict__ ei) {
    if (blockIdx.x >= G64A) {
        int e = (blockIdx.x - G64A) * 256 + threadIdx.x;
        if (e < ETOT) {
            int d = (e < EE) ? ei[EE + e] : (e - EE);
            atomicAdd(&g_deg[d], 1);
        }
        return;
    }
    gemm1_tile(blockIdx.x, X, W, a_s, a_d);
}

// ===== scanA: per-chunk sums =====
__global__ void scanA() {
    __shared__ int sm[256];
    int b = blockIdx.x, t = threadIdx.x;
    int i = b * 256 + t;
    sm[t] = (i < NN) ? g_deg[i] : 0;
    __syncthreads();
    for (int off = 128; off > 0; off >>= 1) {
        if (t < off) sm[t] += sm[t + off];
        __syncthreads();
    }
    if (t == 0) g_bsum[b] = sm[0];
}

// ===== scanBC: each block prefixes bsums (redundant) + scans its chunk =====
__global__ void scanBC() {
    __shared__ int sbs[256];
    __shared__ int sc[256];
    int b = blockIdx.x, t = threadIdx.x;
    sbs[t] = (t < NCHK) ? g_bsum[t] : 0;
    __syncthreads();
    // inclusive Hillis-Steele over 256
    for (int off = 1; off < 256; off <<= 1) {
        int v = (t >= off) ? sbs[t - off] : 0;
        __syncthreads();
        sbs[t] += v;
        __syncthreads();
    }
    int base = (b == 0) ? 0 : sbs[b - 1];
    int i = b * 256 + t;
    int v = (i < NN) ? g_deg[i] : 0;
    sc[t] = v;
    __syncthreads();
    for (int off = 1; off < 256; off <<= 1) {
        int x = (t >= off) ? sc[t - off] : 0;
        __syncthreads();
        sc[t] += x;
        __syncthreads();
    }
    if (i < NN) {
        int excl = base + sc[t] - v;
        g_off[i] = excl;
        g_cur[i] = excl;
        g_deg[i] = 0;
    }
    if (b == NCHK - 1 && t == 255) g_off[NN] = base + sc[255];
}

// ===== K3: scatter || gemm1 tiles [G64A, G64BLK) =====
__global__ void __launch_bounds__(256)
k3_scatter_gemm1b(const float* __restrict__ X, const float* __restrict__ W,
                  const float* __restrict__ a_s, const float* __restrict__ a_d,
                  const int* __restrict__ ei) {
    if (blockIdx.x < EBLK) {
        int e = blockIdx.x * 256 + threadIdx.x;
        if (e < ETOT) {
            int s, d;
            if (e < EE) { s = ei[e]; d = ei[EE + e]; } else { s = e - EE; d = s; }
            int pos = atomicAdd(&g_cur[d], 1);
            g_csr[pos] = s;
        }
        return;
    }
    gemm1_tile(G64A + (blockIdx.x - EBLK), X, W, a_s, a_d);
}

// ------- GEMM 64-wide (layer 2), 128-row tile, fused al + fp16 out ----
template <int IN>
__global__ void __launch_bounds__(256)
gemm64(const float* __restrict__ X, const float* __restrict__ W,
       const float* __restrict__ a_s, const float* __restrict__ a_d) {
    constexpr int KT = 32;
    constexpr int SXS = 132;
    __shared__ float sW[KT][64];
    __shared__ float sX2[KT][SXS];
    int t = threadIdx.x;
    int tx = t & 15, ty = t >> 4;
    int row0 = blockIdx.x * 128;
    float acc[8][4];
#pragma unroll
    for (int r = 0; r < 8; r++)
#pragma unroll
        for (int c = 0; c < 4; c++) acc[r][c] = 0.f;

    for (int kt = 0; kt < IN; kt += KT) {
#pragma unroll
        for (int i = t; i < KT * 16; i += 256) {
            int kk = i >> 4;
            int c4 = (i & 15) << 2;
            *(float4*)&sW[kk][c4] = *(const float4*)&W[(kt + kk) * 64 + c4];
        }
#pragma unroll
        for (int i = t; i < 128 * (KT / 4); i += 256) {
            int r = i >> 3;
            int k4 = (i & 7) << 2;
            int gr = row0 + r;
            float4 v = (gr < NN) ? *(const float4*)&X[gr * IN + kt + k4]
                                 : make_float4(0.f, 0.f, 0.f, 0.f);
            sX2[k4 + 0][r] = v.x;
            sX2[k4 + 1][r] = v.y;
            sX2[k4 + 2][r] = v.z;
            sX2[k4 + 3][r] = v.w;
        }
        __syncthreads();
#pragma unroll
        for (int k = 0; k < KT; k++) {
            float4 w4 = *(float4*)&sW[k][tx * 4];
            float4 xa = *(float4*)&sX2[k][ty * 8];
            float4 xb = *(float4*)&sX2[k][ty * 8 + 4];
            float xr[8] = {xa.x, xa.y, xa.z, xa.w, xb.x, xb.y, xb.z, xb.w};
#pragma unroll
            for (int r = 0; r < 8; r++) {
                acc[r][0] += xr[r] * w4.x;
                acc[r][1] += xr[r] * w4.y;
                acc[r][2] += xr[r] * w4.z;
                acc[r][3] += xr[r] * w4.w;
            }
        }
        __syncthreads();
    }

    int h = tx >> 2;
    float4 asv = *(const float4*)&a_s[h * 16 + (tx & 3) * 4];
    float4 adv = *(const float4*)&a_d[h * 16 + (tx & 3) * 4];
    __half2* h2out = (__half2*)g_h16v;
#pragma unroll
    for (int r = 0; r < 8; r++) {
        int gr = row0 + ty * 8 + r;
        float ps = acc[r][0] * asv.x + acc[r][1] * asv.y + acc[r][2] * asv.z + acc[r][3] * asv.w;
        float pd = acc[r][0] * adv.x + acc[r][1] * adv.y + acc[r][2] * adv.z + acc[r][3] * adv.w;
        ps += __shfl_xor_sync(0xffffffffu, ps, 1);
        ps += __shfl_xor_sync(0xffffffffu, ps, 2);
        pd += __shfl_xor_sync(0xffffffffu, pd, 1);
        pd += __shfl_xor_sync(0xffffffffu, pd, 2);
        if (gr < NN) {
            h2out[(gr * 64 + tx * 4) >> 1] = __floats2half2_rn(acc[r][0], acc[r][1]);
            h2out[((gr * 64 + tx * 4) >> 1) + 1] = __floats2half2_rn(acc[r][2], acc[r][3]);
            if ((tx & 3) == 0) {
                g_als[gr * 4 + h] = ps;
                g_ald[gr * 4 + h] = pd;
            }
        }
    }
}

// ------- GEMM layer 3 (64->16): fused al epilogue, fp16-only output -------
__global__ void gemm16(const float* __restrict__ X, const float* __restrict__ W,
                       const float* __restrict__ a_s, const float* __restrict__ a_d) {
    constexpr int IN = 64, OUT = 16;
    constexpr int RB = 64;
    __shared__ float sW[IN * OUT];
    __shared__ float sX[RB * IN];
    int t = threadIdx.x;
    int tx = t & 15, ty = t >> 4;
    int row0 = blockIdx.x * RB;

    for (int i = t; i < IN * OUT; i += 256) sW[i] = W[i];
    for (int i = t; i < RB * IN; i += 256) {
        int r = row0 + i / IN;
        sX[i] = (r < NN) ? X[r * IN + (i % IN)] : 0.f;
    }
    __syncthreads();

    float acc[4];
#pragma unroll
    for (int rr = 0; rr < 4; rr++) acc[rr] = 0.f;
    const float* xs = &sX[ty * 4 * IN];
    for (int k = 0; k < IN; k++) {
        float wv = sW[k * OUT + tx];
#pragma unroll
        for (int rr = 0; rr < 4; rr++) acc[rr] += xs[rr * IN + k] * wv;
    }
    float asx = __ldg(&a_s[tx]), adx = __ldg(&a_d[tx]);
    __half* h16 = (__half*)g_h16v;
#pragma unroll
    for (int rr = 0; rr < 4; rr++) {
        int r = row0 + ty * 4 + rr;
        float ps = acc[rr] * asx;
        float pd = acc[rr] * adx;
#pragma unroll
        for (int off = 1; off < 16; off <<= 1) {
            ps += __shfl_xor_sync(0xffffffffu, ps, off);
            pd += __shfl_xor_sync(0xffffffffu, pd, off);
        }
        if (r < NN) {
            h16[r * OUT + tx] = __float2half_rn(acc[rr]);
            if (tx == 0) {
                g_als[r] = ps;
                g_ald[r] = pd;
            }
        }
    }
}

__device__ __forceinline__ float lrelu_exp(float v) {
    v = (v > 0.f) ? v : 0.2f * v;
    return __expf(v);
}

// ============ fused gather-aggregation, 64-wide (layers 1 & 2) ============
// warp per dst node; 2 edge-halves of 16 lanes; lane owns 4 cols via LDG.64.
__global__ void __launch_bounds__(256)
agg64(const float* __restrict__ b,
      const float* __restrict__ gg, const float* __restrict__ bb,
      const float* __restrict__ mm, const float* __restrict__ vv,
      float* __restrict__ xnext) {
    __shared__ float2 sh_sex[8][4][34];
    int w = threadIdx.x >> 5;
    int lane = threadIdx.x & 31;
    int n = (blockIdx.x * blockDim.x + threadIdx.x) >> 5;
    if (n >= NN) return;
    int eg = lane >> 4;        // edge half 0/1
    int cq = lane & 15;        // col quad: cols 4*cq .. 4*cq+3
    int h = cq >> 2;           // head of those cols
    float4 ad4 = *(const float4*)&g_ald[n * 4];
    float acc0 = 0.f, acc1 = 0.f, acc2 = 0.f, acc3 = 0.f, den = 0.f;
    const uint2* pu2 = (const uint2*)g_h16v;
    int beg = g_off[n], end = g_off[n + 1];
    for (int base = beg; base < end; base += 32) {
        int idx = base + lane;
        bool valid = idx < end;
        int s = valid ? g_csr[idx] : 0;
        float4 as4 = *(const float4*)&g_als[s * 4];
        float sf = __int_as_float(s * 16);     // row base in uint2 units
        float e0 = valid ? lrelu_exp(as4.x + ad4.x) : 0.f;
        float e1 = valid ? lrelu_exp(as4.y + ad4.y) : 0.f;
        float e2 = valid ? lrelu_exp(as4.z + ad4.z) : 0.f;
        float e3 = valid ? lrelu_exp(as4.w + ad4.w) : 0.f;
        __syncwarp();
        sh_sex[w][0][lane] = make_float2(sf, e0);
        sh_sex[w][1][lane] = make_float2(sf, e1);
        sh_sex[w][2][lane] = make_float2(sf, e2);
        sh_sex[w][3][lane] = make_float2(sf, e3);
        __syncwarp();
        int nk8 = (min(32, end - base) + 7) & ~7;
        for (int j0 = 0; j0 < nk8; j0 += 8) {
#pragma unroll
            for (int u = 0; u < 4; u++) {
                int j = j0 + 2 * u + eg;
                float2 p = sh_sex[w][h][j];
                int sj16 = __float_as_int(p.x);
                float ex = p.y;
                uint2 v = __ldg(&pu2[sj16 + cq]);
                float2 f0 = __half22float2(*(__half2*)&v.x);
                float2 f1 = __half22float2(*(__half2*)&v.y);
                acc0 += ex * f0.x;
                acc1 += ex * f0.y;
                acc2 += ex * f1.x;
                acc3 += ex * f1.y;
                den += ex;
            }
        }
    }
    acc0 += __shfl_xor_sync(0xffffffffu, acc0, 16);
    acc1 += __shfl_xor_sync(0xffffffffu, acc1, 16);
    acc2 += __shfl_xor_sync(0xffffffffu, acc2, 16);
    acc3 += __shfl_xor_sync(0xffffffffu, acc3, 16);
    den += __shfl_xor_sync(0xffffffffu, den, 16);
    if (lane < 16) {
        float inv = 1.f / (den + 1e-16f);
        int c0 = 4 * cq;
        float a[4] = {acc0 * inv, acc1 * inv, acc2 * inv, acc3 * inv};
        float o[4];
#pragma unroll
        for (int i = 0; i < 4; i++) {
            int col = c0 + i;
            float y = (a[i] + __ldg(&b[col]) - __ldg(&mm[col])) *
                          rsqrtf(__ldg(&vv[col]) + 1e-5f) * __ldg(&gg[col]) +
                      __ldg(&bb[col]);
            o[i] = fmaxf(y, 0.f);
        }
        *(float4*)&xnext[n * 64 + c0] = make_float4(o[0], o[1], o[2], o[3]);
    }
}

// ============ fused gather-aggregation, 16-wide (layer 3) ============
// warp per dst node; 8 edge-groups of 4 lanes; lane owns 4 cols via uint2.
__global__ void __launch_bounds__(256)
agg16() {
    __shared__ float2 sh_sex[8][33];
    int w = threadIdx.x >> 5;
    int lane = threadIdx.x & 31;
    int n = (blockIdx.x * blockDim.x + threadIdx.x) >> 5;
    if (n >= NN) return;
    int q = lane >> 2;        // edge-group 0..7
    int cg = lane & 3;        // uint2 col group: cols 4*cg .. 4*cg+3
    float ad = g_ald[n];
    float a0 = 0.f, a1 = 0.f, a2 = 0.f, a3 = 0.f, den = 0.f;
    const uint2* pu2 = (const uint2*)g_h16v;   // row = 16 halves = 4 uint2
    int beg = g_off[n], end = g_off[n + 1];
    for (int base = beg; base < end; base += 32) {
        int idx = base + lane;
        bool valid = idx < end;
        int s = valid ? g_csr[idx] : 0;
        float ex = valid ? lrelu_exp(__ldg(&g_als[s]) + ad) : 0.f;
        __syncwarp();
        sh_sex[w][lane] = make_float2(__int_as_float(s * 4), ex);
        __syncwarp();
        int nk8 = (min(32, end - base) + 7) & ~7;
        for (int j0 = 0; j0 < nk8; j0 += 8) {
            int j = j0 + q;
            float2 p = sh_sex[w][j];
            int sj4 = __float_as_int(p.x);
            float exj = p.y;
            uint2 v = __ldg(&pu2[sj4 + cg]);
            float2 f0 = __half22float2(*(__half2*)&v.x);
            float2 f1 = __half22float2(*(__half2*)&v.y);
            a0 += exj * f0.x;
            a1 += exj * f0.y;
            a2 += exj * f1.x;
            a3 += exj * f1.y;
            den += exj;
        }
    }
#pragma unroll
    for (int off = 4; off <= 16; off <<= 1) {
        a0 += __shfl_xor_sync(0xffffffffu, a0, off);
        a1 += __shfl_xor_sync(0xffffffffu, a1, off);
        a2 += __shfl_xor_sync(0xffffffffu, a2, off);
        a3 += __shfl_xor_sync(0xffffffffu, a3, off);
        den += __shfl_xor_sync(0xffffffffu, den, off);
    }
    if (lane < 4) {
        float inv = 1.f / (den + 1e-16f);
        float4 o = make_float4(a0 * inv, a1 * inv, a2 * inv, a3 * inv);
        *(float4*)&g_acc[n * 16 + 4 * cg] = o;
    }
}

// ---------------- epilogue layer 3 ----------------
__global__ void ep3(const float* __restrict__ b3, const float* __restrict__ gg,
                    const float* __restrict__ bb, const float* __restrict__ mm,
                    const float* __restrict__ vv, const float* __restrict__ fw1,
                    const float* __restrict__ fb1, const float* __restrict__ fw2,
                    const float* __restrict__ fb2, float* __restrict__ out) {
    int n = blockIdx.x * blockDim.x + threadIdx.x;
    if (n >= NN) return;
    float t[16];
#pragma unroll
    for (int c = 0; c < 16; c++) {
        float y = (g_acc[n * 16 + c] + __ldg(&b3[c]) - __ldg(&mm[c])) *
                      rsqrtf(__ldg(&vv[c]) + 1e-5f) * __ldg(&gg[c]) +
                  __ldg(&bb[c]);
        t[c] = fmaxf(y, 0.f);
    }
    float o = __ldg(&fb2[0]);
#pragma unroll
    for (int oo = 0; oo < 8; oo++) {
        float z = __ldg(&fb1[oo]);
#pragma unroll
        for (int c = 0; c < 16; c++) z += t[c] * __ldg(&fw1[c * 8 + oo]);
        z = fmaxf(z, 0.f);
        o += z * __ldg(&fw2[oo]);
    }
    out[n] = o;
}

// ---------------- launch ----------------
extern "C" void kernel_launch(void* const* d_in, const int* in_sizes, int n_in,
                              void* d_out, int out_size) {
    const float* x = (const float*)d_in[0];
    const int* ei = (const int*)d_in[1];
    const float* W1 = (const float*)d_in[2];
    const float* as1 = (const float*)d_in[3];
    const float* ad1 = (const float*)d_in[4];
    const float* b1 = (const float*)d_in[5];
    const float* g1 = (const float*)d_in[6];
    const float* bb1 = (const float*)d_in[7];
    const float* m1 = (const float*)d_in[8];
    const float* v1 = (const float*)d_in[9];
    const float* W2 = (const float*)d_in[10];
    const float* as2 = (const float*)d_in[11];
    const float* ad2 = (const float*)d_in[12];
    const float* b2 = (const float*)d_in[13];
    const float* g2 = (const float*)d_in[14];
    const float* bb2 = (const float*)d_in[15];
    const float* m2 = (const float*)d_in[16];
    const float* v2 = (const float*)d_in[17];
    const float* W3 = (const float*)d_in[18];
    const float* as3 = (const float*)d_in[19];
    const float* ad3 = (const float*)d_in[20];
    const float* b3 = (const float*)d_in[21];
    const float* g3 = (const float*)d_in[22];
    const float* bb3 = (const float*)d_in[23];
    const float* m3 = (const float*)d_in[24];
    const float* v3 = (const float*)d_in[25];
    const float* fw1 = (const float*)d_in[26];
    const float* fb1 = (const float*)d_in[27];
    const float* fw2 = (const float*)d_in[28];
    const float* fb2 = (const float*)d_in[29];
    float* out = (float*)d_out;

    float* px2 = nullptr;
    cudaGetSymbolAddress((void**)&px2, g_x2);

    const int TB = 256;
    int nblk = (NN + TB - 1) / TB;
    int aggblk = (NN * 32 + TB - 1) / TB;

    // ---- Layer 1 preamble: [gemm1-A || hist] -> scanA -> scanBC -> [scatter || gemm1-B]
    k1_gemm1a_hist<<<G64A + EBLK, TB>>>(x, W1, as1, ad1, ei);
    scanA<<<NCHK, 256>>>();
    scanBC<<<NCHK, 256>>>();
    k3_scatter_gemm1b<<<EBLK + G64B, TB>>>(x, W1, as1, ad1, ei);
    agg64<<<aggblk, TB>>>(b1, g1, bb1, m1, v1, px2);

    // ---- Layer 2 ----
    gemm64<64><<<G64BLK, TB>>>(px2, W2, as2, ad2);
    agg64<<<aggblk, TB>>>(b2, g2, bb2, m2, v2, px2);

    // ---- Layer 3 ----
    gemm16<<<(NN + 63) / 64, TB>>>(px2, W3, as3, ad3);
    agg16<<<aggblk, TB>>>();
    ep3<<<nblk, TB>>>(b3, g3, bb3, m3, v3, fw1, fb1, fw2, fb2, out);
}

// round 16
// speedup vs baseline: 1.7001x; 1.0534x over previous
#include <cuda_runtime.h>
#include <cuda_fp16.h>
#include <math.h>

#define NN 50000
#define EE 1600000
#define ETOT (EE + NN)
#define G64BLK ((NN + 127) / 128)          // 391 gemm1 tiles
#define EBLK ((ETOT + 255) / 256)
#define NCHK 196                            // scan chunks of 256 (196*256 >= NN)

// ---------------- scratch ----------------
__device__ uint4  g_h16v[NN * 8];    // fp16 h, 16B-aligned (64 halves per node)
__device__ float  g_x2[NN * 64];
__device__ float  g_als[NN * 4];
__device__ float  g_ald[NN * 4];
__device__ float  g_acc[NN * 16];
__device__ int    g_deg[NN];         // static-zero at start; re-zeroed by scanBC
__device__ int    g_bsum[NCHK];
__device__ int    g_off[NN + 1];
__device__ int    g_cur[NN];
__device__ int    g_csr[ETOT];

// ------------- shared gemm1 tile body (layer 1: 128 -> 64, fused al) --------
__device__ __forceinline__ void gemm1_tile(int tile, const float* __restrict__ X,
                                           const float* __restrict__ W,
                                           const float* __restrict__ a_s,
                                           const float* __restrict__ a_d) {
    constexpr int IN = 128;
    constexpr int KT = 32;
    constexpr int SXS = 132;
    __shared__ float sW[KT][64];
    __shared__ float sX2[KT][SXS];
    int t = threadIdx.x;
    int tx = t & 15, ty = t >> 4;
    int row0 = tile * 128;
    float acc[8][4];
#pragma unroll
    for (int r = 0; r < 8; r++)
#pragma unroll
        for (int c = 0; c < 4; c++) acc[r][c] = 0.f;

    for (int kt = 0; kt < IN; kt += KT) {
#pragma unroll
        for (int i = t; i < KT * 16; i += 256) {
            int kk = i >> 4;
            int c4 = (i & 15) << 2;
            *(float4*)&sW[kk][c4] = *(const float4*)&W[(kt + kk) * 64 + c4];
        }
#pragma unroll
        for (int i = t; i < 128 * (KT / 4); i += 256) {
            int r = i >> 3;
            int k4 = (i & 7) << 2;
            int gr = row0 + r;
            float4 v = (gr < NN) ? *(const float4*)&X[gr * IN + kt + k4]
                                 : make_float4(0.f, 0.f, 0.f, 0.f);
            sX2[k4 + 0][r] = v.x;
            sX2[k4 + 1][r] = v.y;
            sX2[k4 + 2][r] = v.z;
            sX2[k4 + 3][r] = v.w;
        }
        __syncthreads();
#pragma unroll
        for (int k = 0; k < KT; k++) {
            float4 w4 = *(float4*)&sW[k][tx * 4];
            float4 xa = *(float4*)&sX2[k][ty * 8];
            float4 xb = *(float4*)&sX2[k][ty * 8 + 4];
            float xr[8] = {xa.x, xa.y, xa.z, xa.w, xb.x, xb.y, xb.z, xb.w};
#pragma unroll
            for (int r = 0; r < 8; r++) {
                acc[r][0] += xr[r] * w4.x;
                acc[r][1] += xr[r] * w4.y;
                acc[r][2] += xr[r] * w4.z;
                acc[r][3] += xr[r] * w4.w;
            }
        }
        __syncthreads();
    }

    int h = tx >> 2;
    float4 asv = *(const float4*)&a_s[h * 16 + (tx & 3) * 4];
    float4 adv = *(const float4*)&a_d[h * 16 + (tx & 3) * 4];
    __half2* h2out = (__half2*)g_h16v;
#pragma unroll
    for (int r = 0; r < 8; r++) {
        int gr = row0 + ty * 8 + r;
        float ps = acc[r][0] * asv.x + acc[r][1] * asv.y + acc[r][2] * asv.z + acc[r][3] * asv.w;
        float pd = acc[r][0] * adv.x + acc[r][1] * adv.y + acc[r][2] * adv.z + acc[r][3] * adv.w;
        ps += __shfl_xor_sync(0xffffffffu, ps, 1);
        ps += __shfl_xor_sync(0xffffffffu, ps, 2);
        pd += __shfl_xor_sync(0xffffffffu, pd, 1);
        pd += __shfl_xor_sync(0xffffffffu, pd, 2);
        if (gr < NN) {
            h2out[(gr * 64 + tx * 4) >> 1] = __floats2half2_rn(acc[r][0], acc[r][1]);
            h2out[((gr * 64 + tx * 4) >> 1) + 1] = __floats2half2_rn(acc[r][2], acc[r][3]);
            if ((tx & 3) == 0) {
                g_als[gr * 4 + h] = ps;
                g_ald[gr * 4 + h] = pd;
            }
        }
    }
}

// ===== K1: ALL gemm1 tiles [0, G64BLK) || hist =====
__global__ void __launch_bounds__(256)
k1_gemm1_hist(const float* __restrict__ X, const float* __restrict__ W,
              const float* __restrict__ a_s, const float* __restrict__ a_d,
              const int* __restrict__ ei) {
    if (blockIdx.x >= G64BLK) {
        int e = (blockIdx.x - G64BLK) * 256 + threadIdx.x;
        if (e < ETOT) {
            int d = (e < EE) ? ei[EE + e] : (e - EE);
            atomicAdd(&g_deg[d], 1);
        }
        return;
    }
    gemm1_tile(blockIdx.x, X, W, a_s, a_d);
}

// ===== scanA: per-chunk sums =====
__global__ void scanA() {
    __shared__ int sm[256];
    int b = blockIdx.x, t = threadIdx.x;
    int i = b * 256 + t;
    sm[t] = (i < NN) ? g_deg[i] : 0;
    __syncthreads();
    for (int off = 128; off > 0; off >>= 1) {
        if (t < off) sm[t] += sm[t + off];
        __syncthreads();
    }
    if (t == 0) g_bsum[b] = sm[0];
}

// ===== scanBC: each block prefixes bsums (redundant) + scans its chunk =====
__global__ void scanBC() {
    __shared__ int sbs[256];
    __shared__ int sc[256];
    int b = blockIdx.x, t = threadIdx.x;
    sbs[t] = (t < NCHK) ? g_bsum[t] : 0;
    __syncthreads();
    // inclusive Hillis-Steele over 256
    for (int off = 1; off < 256; off <<= 1) {
        int v = (t >= off) ? sbs[t - off] : 0;
        __syncthreads();
        sbs[t] += v;
        __syncthreads();
    }
    int base = (b == 0) ? 0 : sbs[b - 1];
    int i = b * 256 + t;
    int v = (i < NN) ? g_deg[i] : 0;
    sc[t] = v;
    __syncthreads();
    for (int off = 1; off < 256; off <<= 1) {
        int x = (t >= off) ? sc[t - off] : 0;
        __syncthreads();
        sc[t] += x;
        __syncthreads();
    }
    if (i < NN) {
        int excl = base + sc[t] - v;
        g_off[i] = excl;
        g_cur[i] = excl;
        g_deg[i] = 0;
    }
    if (b == NCHK - 1 && t == 255) g_off[NN] = base + sc[255];
}

// ===== scatter: standalone, lean registers, high occupancy =====
__global__ void __launch_bounds__(256)
scatter_kernel(const int* __restrict__ ei) {
    int e = blockIdx.x * 256 + threadIdx.x;
    if (e >= ETOT) return;
    int s, d;
    if (e < EE) { s = ei[e]; d = ei[EE + e]; } else { s = e - EE; d = s; }
    int pos = atomicAdd(&g_cur[d], 1);
    g_csr[pos] = s;
}

// ------- GEMM 64-wide (layer 2), 128-row tile, fused al + fp16 out ----
template <int IN>
__global__ void __launch_bounds__(256)
gemm64(const float* __restrict__ X, const float* __restrict__ W,
       const float* __restrict__ a_s, const float* __restrict__ a_d) {
    constexpr int KT = 32;
    constexpr int SXS = 132;
    __shared__ float sW[KT][64];
    __shared__ float sX2[KT][SXS];
    int t = threadIdx.x;
    int tx = t & 15, ty = t >> 4;
    int row0 = blockIdx.x * 128;
    float acc[8][4];
#pragma unroll
    for (int r = 0; r < 8; r++)
#pragma unroll
        for (int c = 0; c < 4; c++) acc[r][c] = 0.f;

    for (int kt = 0; kt < IN; kt += KT) {
#pragma unroll
        for (int i = t; i < KT * 16; i += 256) {
            int kk = i >> 4;
            int c4 = (i & 15) << 2;
            *(float4*)&sW[kk][c4] = *(const float4*)&W[(kt + kk) * 64 + c4];
        }
#pragma unroll
        for (int i = t; i < 128 * (KT / 4); i += 256) {
            int r = i >> 3;
            int k4 = (i & 7) << 2;
            int gr = row0 + r;
            float4 v = (gr < NN) ? *(const float4*)&X[gr * IN + kt + k4]
                                 : make_float4(0.f, 0.f, 0.f, 0.f);
            sX2[k4 + 0][r] = v.x;
            sX2[k4 + 1][r] = v.y;
            sX2[k4 + 2][r] = v.z;
            sX2[k4 + 3][r] = v.w;
        }
        __syncthreads();
#pragma unroll
        for (int k = 0; k < KT; k++) {
            float4 w4 = *(float4*)&sW[k][tx * 4];
            float4 xa = *(float4*)&sX2[k][ty * 8];
            float4 xb = *(float4*)&sX2[k][ty * 8 + 4];
            float xr[8] = {xa.x, xa.y, xa.z, xa.w, xb.x, xb.y, xb.z, xb.w};
#pragma unroll
            for (int r = 0; r < 8; r++) {
                acc[r][0] += xr[r] * w4.x;
                acc[r][1] += xr[r] * w4.y;
                acc[r][2] += xr[r] * w4.z;
                acc[r][3] += xr[r] * w4.w;
            }
        }
        __syncthreads();
    }

    int h = tx >> 2;
    float4 asv = *(const float4*)&a_s[h * 16 + (tx & 3) * 4];
    float4 adv = *(const float4*)&a_d[h * 16 + (tx & 3) * 4];
    __half2* h2out = (__half2*)g_h16v;
#pragma unroll
    for (int r = 0; r < 8; r++) {
        int gr = row0 + ty * 8 + r;
        float ps = acc[r][0] * asv.x + acc[r][1] * asv.y + acc[r][2] * asv.z + acc[r][3] * asv.w;
        float pd = acc[r][0] * adv.x + acc[r][1] * adv.y + acc[r][2] * adv.z + acc[r][3] * adv.w;
        ps += __shfl_xor_sync(0xffffffffu, ps, 1);
        ps += __shfl_xor_sync(0xffffffffu, ps, 2);
        pd += __shfl_xor_sync(0xffffffffu, pd, 1);
        pd += __shfl_xor_sync(0xffffffffu, pd, 2);
        if (gr < NN) {
            h2out[(gr * 64 + tx * 4) >> 1] = __floats2half2_rn(acc[r][0], acc[r][1]);
            h2out[((gr * 64 + tx * 4) >> 1) + 1] = __floats2half2_rn(acc[r][2], acc[r][3]);
            if ((tx & 3) == 0) {
                g_als[gr * 4 + h] = ps;
                g_ald[gr * 4 + h] = pd;
            }
        }
    }
}

// ------- GEMM layer 3 (64->16): fused al epilogue, fp16-only output -------
__global__ void gemm16(const float* __restrict__ X, const float* __restrict__ W,
                       const float* __restrict__ a_s, const float* __restrict__ a_d) {
    constexpr int IN = 64, OUT = 16;
    constexpr int RB = 64;
    __shared__ float sW[IN * OUT];
    __shared__ float sX[RB * IN];
    int t = threadIdx.x;
    int tx = t & 15, ty = t >> 4;
    int row0 = blockIdx.x * RB;

    for (int i = t; i < IN * OUT; i += 256) sW[i] = W[i];
    for (int i = t; i < RB * IN; i += 256) {
        int r = row0 + i / IN;
        sX[i] = (r < NN) ? X[r * IN + (i % IN)] : 0.f;
    }
    __syncthreads();

    float acc[4];
#pragma unroll
    for (int rr = 0; rr < 4; rr++) acc[rr] = 0.f;
    const float* xs = &sX[ty * 4 * IN];
    for (int k = 0; k < IN; k++) {
        float wv = sW[k * OUT + tx];
#pragma unroll
        for (int rr = 0; rr < 4; rr++) acc[rr] += xs[rr * IN + k] * wv;
    }
    float asx = __ldg(&a_s[tx]), adx = __ldg(&a_d[tx]);
    __half* h16 = (__half*)g_h16v;
#pragma unroll
    for (int rr = 0; rr < 4; rr++) {
        int r = row0 + ty * 4 + rr;
        float ps = acc[rr] * asx;
        float pd = acc[rr] * adx;
#pragma unroll
        for (int off = 1; off < 16; off <<= 1) {
            ps += __shfl_xor_sync(0xffffffffu, ps, off);
            pd += __shfl_xor_sync(0xffffffffu, pd, off);
        }
        if (r < NN) {
            h16[r * OUT + tx] = __float2half_rn(acc[rr]);
            if (tx == 0) {
                g_als[r] = ps;
                g_ald[r] = pd;
            }
        }
    }
}

__device__ __forceinline__ float lrelu_exp(float v) {
    v = (v > 0.f) ? v : 0.2f * v;
    return __expf(v);
}

// ============ fused gather-aggregation, 64-wide (layers 1 & 2) ============
// warp per dst node; 2 edge-halves of 16 lanes; lane owns 4 cols via LDG.64.
__global__ void __launch_bounds__(256)
agg64(const float* __restrict__ b,
      const float* __restrict__ gg, const float* __restrict__ bb,
      const float* __restrict__ mm, const float* __restrict__ vv,
      float* __restrict__ xnext) {
    __shared__ float2 sh_sex[8][4][34];
    int w = threadIdx.x >> 5;
    int lane = threadIdx.x & 31;
    int n = (blockIdx.x * blockDim.x + threadIdx.x) >> 5;
    if (n >= NN) return;
    int eg = lane >> 4;        // edge half 0/1
    int cq = lane & 15;        // col quad: cols 4*cq .. 4*cq+3
    int h = cq >> 2;           // head of those cols
    float4 ad4 = *(const float4*)&g_ald[n * 4];
    float acc0 = 0.f, acc1 = 0.f, acc2 = 0.f, acc3 = 0.f, den = 0.f;
    const uint2* pu2 = (const uint2*)g_h16v;
    int beg = g_off[n], end = g_off[n + 1];
    for (int base = beg; base < end; base += 32) {
        int idx = base + lane;
        bool valid = idx < end;
        int s = valid ? g_csr[idx] : 0;
        float4 as4 = *(const float4*)&g_als[s * 4];
        float sf = __int_as_float(s * 16);     // row base in uint2 units
        float e0 = valid ? lrelu_exp(as4.x + ad4.x) : 0.f;
        float e1 = valid ? lrelu_exp(as4.y + ad4.y) : 0.f;
        float e2 = valid ? lrelu_exp(as4.z + ad4.z) : 0.f;
        float e3 = valid ? lrelu_exp(as4.w + ad4.w) : 0.f;
        __syncwarp();
        sh_sex[w][0][lane] = make_float2(sf, e0);
        sh_sex[w][1][lane] = make_float2(sf, e1);
        sh_sex[w][2][lane] = make_float2(sf, e2);
        sh_sex[w][3][lane] = make_float2(sf, e3);
        __syncwarp();
        int nk8 = (min(32, end - base) + 7) & ~7;
        for (int j0 = 0; j0 < nk8; j0 += 8) {
#pragma unroll
            for (int u = 0; u < 4; u++) {
                int j = j0 + 2 * u + eg;
                float2 p = sh_sex[w][h][j];
                int sj16 = __float_as_int(p.x);
                float ex = p.y;
                uint2 v = __ldg(&pu2[sj16 + cq]);
                float2 f0 = __half22float2(*(__half2*)&v.x);
                float2 f1 = __half22float2(*(__half2*)&v.y);
                acc0 += ex * f0.x;
                acc1 += ex * f0.y;
                acc2 += ex * f1.x;
                acc3 += ex * f1.y;
                den += ex;
            }
        }
    }
    acc0 += __shfl_xor_sync(0xffffffffu, acc0, 16);
    acc1 += __shfl_xor_sync(0xffffffffu, acc1, 16);
    acc2 += __shfl_xor_sync(0xffffffffu, acc2, 16);
    acc3 += __shfl_xor_sync(0xffffffffu, acc3, 16);
    den += __shfl_xor_sync(0xffffffffu, den, 16);
    if (lane < 16) {
        float inv = 1.f / (den + 1e-16f);
        int c0 = 4 * cq;
        float a[4] = {acc0 * inv, acc1 * inv, acc2 * inv, acc3 * inv};
        float o[4];
#pragma unroll
        for (int i = 0; i < 4; i++) {
            int col = c0 + i;
            float y = (a[i] + __ldg(&b[col]) - __ldg(&mm[col])) *
                          rsqrtf(__ldg(&vv[col]) + 1e-5f) * __ldg(&gg[col]) +
                      __ldg(&bb[col]);
            o[i] = fmaxf(y, 0.f);
        }
        *(float4*)&xnext[n * 64 + c0] = make_float4(o[0], o[1], o[2], o[3]);
    }
}

// ============ fused gather-aggregation, 16-wide (layer 3) ============
// warp per dst node; 8 edge-groups of 4 lanes; lane owns 4 cols via uint2.
__global__ void __launch_bounds__(256)
agg16() {
    __shared__ float2 sh_sex[8][33];
    int w = threadIdx.x >> 5;
    int lane = threadIdx.x & 31;
    int n = (blockIdx.x * blockDim.x + threadIdx.x) >> 5;
    if (n >= NN) return;
    int q = lane >> 2;        // edge-group 0..7
    int cg = lane & 3;        // uint2 col group: cols 4*cg .. 4*cg+3
    float ad = g_ald[n];
    float a0 = 0.f, a1 = 0.f, a2 = 0.f, a3 = 0.f, den = 0.f;
    const uint2* pu2 = (const uint2*)g_h16v;   // row = 16 halves = 4 uint2
    int beg = g_off[n], end = g_off[n + 1];
    for (int base = beg; base < end; base += 32) {
        int idx = base + lane;
        bool valid = idx < end;
        int s = valid ? g_csr[idx] : 0;
        float ex = valid ? lrelu_exp(__ldg(&g_als[s]) + ad) : 0.f;
        __syncwarp();
        sh_sex[w][lane] = make_float2(__int_as_float(s * 4), ex);
        __syncwarp();
        int nk8 = (min(32, end - base) + 7) & ~7;
        for (int j0 = 0; j0 < nk8; j0 += 8) {
            int j = j0 + q;
            float2 p = sh_sex[w][j];
            int sj4 = __float_as_int(p.x);
            float exj = p.y;
            uint2 v = __ldg(&pu2[sj4 + cg]);
            float2 f0 = __half22float2(*(__half2*)&v.x);
            float2 f1 = __half22float2(*(__half2*)&v.y);
            a0 += exj * f0.x;
            a1 += exj * f0.y;
            a2 += exj * f1.x;
            a3 += exj * f1.y;
            den += exj;
        }
    }
#pragma unroll
    for (int off = 4; off <= 16; off <<= 1) {
        a0 += __shfl_xor_sync(0xffffffffu, a0, off);
        a1 += __shfl_xor_sync(0xffffffffu, a1, off);
        a2 += __shfl_xor_sync(0xffffffffu, a2, off);
        a3 += __shfl_xor_sync(0xffffffffu, a3, off);
        den += __shfl_xor_sync(0xffffffffu, den, off);
    }
    if (lane < 4) {
        float inv = 1.f / (den + 1e-16f);
        float4 o = make_float4(a0 * inv, a1 * inv, a2 * inv, a3 * inv);
        *(float4*)&g_acc[n * 16 + 4 * cg] = o;
    }
}

// ---------------- epilogue layer 3 ----------------
__global__ void ep3(const float* __restrict__ b3, const float* __restrict__ gg,
                    const float* __restrict__ bb, const float* __restrict__ mm,
                    const float* __restrict__ vv, const float* __restrict__ fw1,
                    const float* __restrict__ fb1, const float* __restrict__ fw2,
                    const float* __restrict__ fb2, float* __restrict__ out) {
    int n = blockIdx.x * blockDim.x + threadIdx.x;
    if (n >= NN) return;
    float t[16];
#pragma unroll
    for (int c = 0; c < 16; c++) {
        float y = (g_acc[n * 16 + c] + __ldg(&b3[c]) - __ldg(&mm[c])) *
                      rsqrtf(__ldg(&vv[c]) + 1e-5f) * __ldg(&gg[c]) +
                  __ldg(&bb[c]);
        t[c] = fmaxf(y, 0.f);
    }
    float o = __ldg(&fb2[0]);
#pragma unroll
    for (int oo = 0; oo < 8; oo++) {
        float z = __ldg(&fb1[oo]);
#pragma unroll
        for (int c = 0; c < 16; c++) z += t[c] * __ldg(&fw1[c * 8 + oo]);
        z = fmaxf(z, 0.f);
        o += z * __ldg(&fw2[oo]);
    }
    out[n] = o;
}

// ---------------- launch ----------------
extern "C" void kernel_launch(void* const* d_in, const int* in_sizes, int n_in,
                              void* d_out, int out_size) {
    const float* x = (const float*)d_in[0];
    const int* ei = (const int*)d_in[1];
    const float* W1 = (const float*)d_in[2];
    const float* as1 = (const float*)d_in[3];
    const float* ad1 = (const float*)d_in[4];
    const float* b1 = (const float*)d_in[5];
    const float* g1 = (const float*)d_in[6];
    const float* bb1 = (const float*)d_in[7];
    const float* m1 = (const float*)d_in[8];
    const float* v1 = (const float*)d_in[9];
    const float* W2 = (const float*)d_in[10];
    const float* as2 = (const float*)d_in[11];
    const float* ad2 = (const float*)d_in[12];
    const float* b2 = (const float*)d_in[13];
    const float* g2 = (const float*)d_in[14];
    const float* bb2 = (const float*)d_in[15];
    const float* m2 = (const float*)d_in[16];
    const float* v2 = (const float*)d_in[17];
    const float* W3 = (const float*)d_in[18];
    const float* as3 = (const float*)d_in[19];
    const float* ad3 = (const float*)d_in[20];
    const float* b3 = (const float*)d_in[21];
    const float* g3 = (const float*)d_in[22];
    const float* bb3 = (const float*)d_in[23];
    const float* m3 = (const float*)d_in[24];
    const float* v3 = (const float*)d_in[25];
    const float* fw1 = (const float*)d_in[26];
    const float* fb1 = (const float*)d_in[27];
    const float* fw2 = (const float*)d_in[28];
    const float* fb2 = (const float*)d_in[29];
    float* out = (float*)d_out;

    float* px2 = nullptr;
    cudaGetSymbolAddress((void**)&px2, g_x2);

    const int TB = 256;
    int nblk = (NN + TB - 1) / TB;
    int aggblk = (NN * 32 + TB - 1) / TB;

    // ---- Layer 1 preamble: [full gemm1 || hist] -> scanA -> scanBC -> scatter
    k1_gemm1_hist<<<G64BLK + EBLK, TB>>>(x, W1, as1, ad1, ei);
    scanA<<<NCHK, 256>>>();
    scanBC<<<NCHK, 256>>>();
    scatter_kernel<<<EBLK, TB>>>(ei);
    agg64<<<aggblk, TB>>>(b1, g1, bb1, m1, v1, px2);

    // ---- Layer 2 ----
    gemm64<64><<<G64BLK, TB>>>(px2, W2, as2, ad2);
    agg64<<<aggblk, TB>>>(b2, g2, bb2, m2, v2, px2);

    // ---- Layer 3 ----
    gemm16<<<(NN + 63) / 64, TB>>>(px2, W3, as3, ad3);
    agg16<<<aggblk, TB>>>();
    ep3<<<nblk, TB>>>(b3, g3, bb3, m3, v3, fw1, fb1, fw2, fb2, out);
}

// round 17
// speedup vs baseline: 1.7101x; 1.0059x over previous
#include <cuda_runtime.h>
#include <cuda_fp16.h>
#include <math.h>

#define NN 50000
#define EE 1600000
#define ETOT (EE + NN)
#define G64BLK ((NN + 127) / 128)          // 391 gemm1 tiles
#define EBLK ((ETOT + 255) / 256)
#define NCHK 196                            // scan chunks of 256 (196*256 >= NN)

// ---------------- scratch ----------------
__device__ uint4  g_h16v[NN * 8];    // fp16 h, 16B-aligned (64 halves per node)
__device__ float  g_x2[NN * 64];
__device__ float  g_als[NN * 4];
__device__ float  g_ald[NN * 4];
__device__ float  g_acc[NN * 16];
__device__ int    g_deg[NN];         // static-zero at start; re-zeroed by scanBC
__device__ int    g_bsum[NCHK];
__device__ int    g_off[NN + 1];
__device__ int    g_rank[ETOT];      // per-edge rank within its destination
__device__ int    g_csr[ETOT];

// ------------- shared gemm1 tile body (layer 1: 128 -> 64, fused al) --------
__device__ __forceinline__ void gemm1_tile(int tile, const float* __restrict__ X,
                                           const float* __restrict__ W,
                                           const float* __restrict__ a_s,
                                           const float* __restrict__ a_d) {
    constexpr int IN = 128;
    constexpr int KT = 32;
    constexpr int SXS = 132;
    __shared__ float sW[KT][64];
    __shared__ float sX2[KT][SXS];
    int t = threadIdx.x;
    int tx = t & 15, ty = t >> 4;
    int row0 = tile * 128;
    float acc[8][4];
#pragma unroll
    for (int r = 0; r < 8; r++)
#pragma unroll
        for (int c = 0; c < 4; c++) acc[r][c] = 0.f;

    for (int kt = 0; kt < IN; kt += KT) {
#pragma unroll
        for (int i = t; i < KT * 16; i += 256) {
            int kk = i >> 4;
            int c4 = (i & 15) << 2;
            *(float4*)&sW[kk][c4] = *(const float4*)&W[(kt + kk) * 64 + c4];
        }
#pragma unroll
        for (int i = t; i < 128 * (KT / 4); i += 256) {
            int r = i >> 3;
            int k4 = (i & 7) << 2;
            int gr = row0 + r;
            float4 v = (gr < NN) ? *(const float4*)&X[gr * IN + kt + k4]
                                 : make_float4(0.f, 0.f, 0.f, 0.f);
            sX2[k4 + 0][r] = v.x;
            sX2[k4 + 1][r] = v.y;
            sX2[k4 + 2][r] = v.z;
            sX2[k4 + 3][r] = v.w;
        }
        __syncthreads();
#pragma unroll
        for (int k = 0; k < KT; k++) {
            float4 w4 = *(float4*)&sW[k][tx * 4];
            float4 xa = *(float4*)&sX2[k][ty * 8];
            float4 xb = *(float4*)&sX2[k][ty * 8 + 4];
            float xr[8] = {xa.x, xa.y, xa.z, xa.w, xb.x, xb.y, xb.z, xb.w};
#pragma unroll
            for (int r = 0; r < 8; r++) {
                acc[r][0] += xr[r] * w4.x;
                acc[r][1] += xr[r] * w4.y;
                acc[r][2] += xr[r] * w4.z;
                acc[r][3] += xr[r] * w4.w;
            }
        }
        __syncthreads();
    }

    int h = tx >> 2;
    float4 asv = *(const float4*)&a_s[h * 16 + (tx & 3) * 4];
    float4 adv = *(const float4*)&a_d[h * 16 + (tx & 3) * 4];
    __half2* h2out = (__half2*)g_h16v;
#pragma unroll
    for (int r = 0; r < 8; r++) {
        int gr = row0 + ty * 8 + r;
        float ps = acc[r][0] * asv.x + acc[r][1] * asv.y + acc[r][2] * asv.z + acc[r][3] * asv.w;
        float pd = acc[r][0] * adv.x + acc[r][1] * adv.y + acc[r][2] * adv.z + acc[r][3] * adv.w;
        ps += __shfl_xor_sync(0xffffffffu, ps, 1);
        ps += __shfl_xor_sync(0xffffffffu, ps, 2);
        pd += __shfl_xor_sync(0xffffffffu, pd, 1);
        pd += __shfl_xor_sync(0xffffffffu, pd, 2);
        if (gr < NN) {
            h2out[(gr * 64 + tx * 4) >> 1] = __floats2half2_rn(acc[r][0], acc[r][1]);
            h2out[((gr * 64 + tx * 4) >> 1) + 1] = __floats2half2_rn(acc[r][2], acc[r][3]);
            if ((tx & 3) == 0) {
                g_als[gr * 4 + h] = ps;
                g_ald[gr * 4 + h] = pd;
            }
        }
    }
}

// ===== K1: ALL gemm1 tiles [0, G64BLK) || hist (records per-edge rank) =====
__global__ void __launch_bounds__(256)
k1_gemm1_hist(const float* __restrict__ X, const float* __restrict__ W,
              const float* __restrict__ a_s, const float* __restrict__ a_d,
              const int* __restrict__ ei) {
    if (blockIdx.x >= G64BLK) {
        int e = (blockIdx.x - G64BLK) * 256 + threadIdx.x;
        if (e < ETOT) {
            int d = (e < EE) ? ei[EE + e] : (e - EE);
            g_rank[e] = atomicAdd(&g_deg[d], 1);
        }
        return;
    }
    gemm1_tile(blockIdx.x, X, W, a_s, a_d);
}

// ===== scanA: per-chunk sums =====
__global__ void scanA() {
    __shared__ int sm[256];
    int b = blockIdx.x, t = threadIdx.x;
    int i = b * 256 + t;
    sm[t] = (i < NN) ? g_deg[i] : 0;
    __syncthreads();
    for (int off = 128; off > 0; off >>= 1) {
        if (t < off) sm[t] += sm[t + off];
        __syncthreads();
    }
    if (t == 0) g_bsum[b] = sm[0];
}

// ===== scanBC: each block prefixes bsums (redundant) + scans its chunk =====
__global__ void scanBC() {
    __shared__ int sbs[256];
    __shared__ int sc[256];
    int b = blockIdx.x, t = threadIdx.x;
    sbs[t] = (t < NCHK) ? g_bsum[t] : 0;
    __syncthreads();
    // inclusive Hillis-Steele over 256
    for (int off = 1; off < 256; off <<= 1) {
        int v = (t >= off) ? sbs[t - off] : 0;
        __syncthreads();
        sbs[t] += v;
        __syncthreads();
    }
    int base = (b == 0) ? 0 : sbs[b - 1];
    int i = b * 256 + t;
    int v = (i < NN) ? g_deg[i] : 0;
    sc[t] = v;
    __syncthreads();
    for (int off = 1; off < 256; off <<= 1) {
        int x = (t >= off) ? sc[t - off] : 0;
        __syncthreads();
        sc[t] += x;
        __syncthreads();
    }
    if (i < NN) {
        int excl = base + sc[t] - v;
        g_off[i] = excl;
        g_deg[i] = 0;
    }
    if (b == NCHK - 1 && t == 255) g_off[NN] = base + sc[255];
}

// ===== scatter: atomic-free (rank precomputed in hist) =====
__global__ void __launch_bounds__(256)
scatter_kernel(const int* __restrict__ ei) {
    int e = blockIdx.x * 256 + threadIdx.x;
    if (e >= ETOT) return;
    int s, d;
    if (e < EE) { s = ei[e]; d = ei[EE + e]; } else { s = e - EE; d = s; }
    g_csr[__ldg(&g_off[d]) + g_rank[e]] = s;
}

// ------- GEMM 64-wide (layer 2), 128-row tile, fused al + fp16 out ----
template <int IN>
__global__ void __launch_bounds__(256)
gemm64(const float* __restrict__ X, const float* __restrict__ W,
       const float* __restrict__ a_s, const float* __restrict__ a_d) {
    constexpr int KT = 32;
    constexpr int SXS = 132;
    __shared__ float sW[KT][64];
    __shared__ float sX2[KT][SXS];
    int t = threadIdx.x;
    int tx = t & 15, ty = t >> 4;
    int row0 = blockIdx.x * 128;
    float acc[8][4];
#pragma unroll
    for (int r = 0; r < 8; r++)
#pragma unroll
        for (int c = 0; c < 4; c++) acc[r][c] = 0.f;

    for (int kt = 0; kt < IN; kt += KT) {
#pragma unroll
        for (int i = t; i < KT * 16; i += 256) {
            int kk = i >> 4;
            int c4 = (i & 15) << 2;
            *(float4*)&sW[kk][c4] = *(const float4*)&W[(kt + kk) * 64 + c4];
        }
#pragma unroll
        for (int i = t; i < 128 * (KT / 4); i += 256) {
            int r = i >> 3;
            int k4 = (i & 7) << 2;
            int gr = row0 + r;
            float4 v = (gr < NN) ? *(const float4*)&X[gr * IN + kt + k4]
                                 : make_float4(0.f, 0.f, 0.f, 0.f);
            sX2[k4 + 0][r] = v.x;
            sX2[k4 + 1][r] = v.y;
            sX2[k4 + 2][r] = v.z;
            sX2[k4 + 3][r] = v.w;
        }
        __syncthreads();
#pragma unroll
        for (int k = 0; k < KT; k++) {
            float4 w4 = *(float4*)&sW[k][tx * 4];
            float4 xa = *(float4*)&sX2[k][ty * 8];
            float4 xb = *(float4*)&sX2[k][ty * 8 + 4];
            float xr[8] = {xa.x, xa.y, xa.z, xa.w, xb.x, xb.y, xb.z, xb.w};
#pragma unroll
            for (int r = 0; r < 8; r++) {
                acc[r][0] += xr[r] * w4.x;
                acc[r][1] += xr[r] * w4.y;
                acc[r][2] += xr[r] * w4.z;
                acc[r][3] += xr[r] * w4.w;
            }
        }
        __syncthreads();
    }

    int h = tx >> 2;
    float4 asv = *(const float4*)&a_s[h * 16 + (tx & 3) * 4];
    float4 adv = *(const float4*)&a_d[h * 16 + (tx & 3) * 4];
    __half2* h2out = (__half2*)g_h16v;
#pragma unroll
    for (int r = 0; r < 8; r++) {
        int gr = row0 + ty * 8 + r;
        float ps = acc[r][0] * asv.x + acc[r][1] * asv.y + acc[r][2] * asv.z + acc[r][3] * asv.w;
        float pd = acc[r][0] * adv.x + acc[r][1] * adv.y + acc[r][2] * adv.z + acc[r][3] * adv.w;
        ps += __shfl_xor_sync(0xffffffffu, ps, 1);
        ps += __shfl_xor_sync(0xffffffffu, ps, 2);
        pd += __shfl_xor_sync(0xffffffffu, pd, 1);
        pd += __shfl_xor_sync(0xffffffffu, pd, 2);
        if (gr < NN) {
            h2out[(gr * 64 + tx * 4) >> 1] = __floats2half2_rn(acc[r][0], acc[r][1]);
            h2out[((gr * 64 + tx * 4) >> 1) + 1] = __floats2half2_rn(acc[r][2], acc[r][3]);
            if ((tx & 3) == 0) {
                g_als[gr * 4 + h] = ps;
                g_ald[gr * 4 + h] = pd;
            }
        }
    }
}

// ------- GEMM layer 3 (64->16): fused al epilogue, fp16-only output -------
__global__ void gemm16(const float* __restrict__ X, const float* __restrict__ W,
                       const float* __restrict__ a_s, const float* __restrict__ a_d) {
    constexpr int IN = 64, OUT = 16;
    constexpr int RB = 64;
    __shared__ float sW[IN * OUT];
    __shared__ float sX[RB * IN];
    int t = threadIdx.x;
    int tx = t & 15, ty = t >> 4;
    int row0 = blockIdx.x * RB;

    for (int i = t; i < IN * OUT; i += 256) sW[i] = W[i];
    for (int i = t; i < RB * IN; i += 256) {
        int r = row0 + i / IN;
        sX[i] = (r < NN) ? X[r * IN + (i % IN)] : 0.f;
    }
    __syncthreads();

    float acc[4];
#pragma unroll
    for (int rr = 0; rr < 4; rr++) acc[rr] = 0.f;
    const float* xs = &sX[ty * 4 * IN];
    for (int k = 0; k < IN; k++) {
        float wv = sW[k * OUT + tx];
#pragma unroll
        for (int rr = 0; rr < 4; rr++) acc[rr] += xs[rr * IN + k] * wv;
    }
    float asx = __ldg(&a_s[tx]), adx = __ldg(&a_d[tx]);
    __half* h16 = (__half*)g_h16v;
#pragma unroll
    for (int rr = 0; rr < 4; rr++) {
        int r = row0 + ty * 4 + rr;
        float ps = acc[rr] * asx;
        float pd = acc[rr] * adx;
#pragma unroll
        for (int off = 1; off < 16; off <<= 1) {
            ps += __shfl_xor_sync(0xffffffffu, ps, off);
            pd += __shfl_xor_sync(0xffffffffu, pd, off);
        }
        if (r < NN) {
            h16[r * OUT + tx] = __float2half_rn(acc[rr]);
            if (tx == 0) {
                g_als[r] = ps;
                g_ald[r] = pd;
            }
        }
    }
}

__device__ __forceinline__ float lrelu_exp(float v) {
    v = (v > 0.f) ? v : 0.2f * v;
    return __expf(v);
}

// ============ fused gather-aggregation, 64-wide (layers 1 & 2) ============
// warp per dst node; 2 edge-halves of 16 lanes; lane owns 4 cols via LDG.64.
__global__ void __launch_bounds__(256)
agg64(const float* __restrict__ b,
      const float* __restrict__ gg, const float* __restrict__ bb,
      const float* __restrict__ mm, const float* __restrict__ vv,
      float* __restrict__ xnext) {
    __shared__ float2 sh_sex[8][4][34];
    int w = threadIdx.x >> 5;
    int lane = threadIdx.x & 31;
    int n = (blockIdx.x * blockDim.x + threadIdx.x) >> 5;
    if (n >= NN) return;
    int eg = lane >> 4;        // edge half 0/1
    int cq = lane & 15;        // col quad: cols 4*cq .. 4*cq+3
    int h = cq >> 2;           // head of those cols
    float4 ad4 = *(const float4*)&g_ald[n * 4];
    float acc0 = 0.f, acc1 = 0.f, acc2 = 0.f, acc3 = 0.f, den = 0.f;
    const uint2* pu2 = (const uint2*)g_h16v;
    int beg = g_off[n], end = g_off[n + 1];
    for (int base = beg; base < end; base += 32) {
        int idx = base + lane;
        bool valid = idx < end;
        int s = valid ? g_csr[idx] : 0;
        float4 as4 = *(const float4*)&g_als[s * 4];
        float sf = __int_as_float(s * 16);     // row base in uint2 units
        float e0 = valid ? lrelu_exp(as4.x + ad4.x) : 0.f;
        float e1 = valid ? lrelu_exp(as4.y + ad4.y) : 0.f;
        float e2 = valid ? lrelu_exp(as4.z + ad4.z) : 0.f;
        float e3 = valid ? lrelu_exp(as4.w + ad4.w) : 0.f;
        __syncwarp();
        sh_sex[w][0][lane] = make_float2(sf, e0);
        sh_sex[w][1][lane] = make_float2(sf, e1);
        sh_sex[w][2][lane] = make_float2(sf, e2);
        sh_sex[w][3][lane] = make_float2(sf, e3);
        __syncwarp();
        int nk8 = (min(32, end - base) + 7) & ~7;
        for (int j0 = 0; j0 < nk8; j0 += 8) {
#pragma unroll
            for (int u = 0; u < 4; u++) {
                int j = j0 + 2 * u + eg;
                float2 p = sh_sex[w][h][j];
                int sj16 = __float_as_int(p.x);
                float ex = p.y;
                uint2 v = __ldg(&pu2[sj16 + cq]);
                float2 f0 = __half22float2(*(__half2*)&v.x);
                float2 f1 = __half22float2(*(__half2*)&v.y);
                acc0 += ex * f0.x;
                acc1 += ex * f0.y;
                acc2 += ex * f1.x;
                acc3 += ex * f1.y;
                den += ex;
            }
        }
    }
    acc0 += __shfl_xor_sync(0xffffffffu, acc0, 16);
    acc1 += __shfl_xor_sync(0xffffffffu, acc1, 16);
    acc2 += __shfl_xor_sync(0xffffffffu, acc2, 16);
    acc3 += __shfl_xor_sync(0xffffffffu, acc3, 16);
    den += __shfl_xor_sync(0xffffffffu, den, 16);
    if (lane < 16) {
        float inv = 1.f / (den + 1e-16f);
        int c0 = 4 * cq;
        float a[4] = {acc0 * inv, acc1 * inv, acc2 * inv, acc3 * inv};
        float o[4];
#pragma unroll
        for (int i = 0; i < 4; i++) {
            int col = c0 + i;
            float y = (a[i] + __ldg(&b[col]) - __ldg(&mm[col])) *
                          rsqrtf(__ldg(&vv[col]) + 1e-5f) * __ldg(&gg[col]) +
                      __ldg(&bb[col]);
            o[i] = fmaxf(y, 0.f);
        }
        *(float4*)&xnext[n * 64 + c0] = make_float4(o[0], o[1], o[2], o[3]);
    }
}

// ============ fused gather-aggregation, 16-wide (layer 3) ============
// warp per dst node; 8 edge-groups of 4 lanes; lane owns 4 cols via uint2.
__global__ void __launch_bounds__(256)
agg16() {
    __shared__ float2 sh_sex[8][33];
    int w = threadIdx.x >> 5;
    int lane = threadIdx.x & 31;
    int n = (blockIdx.x * blockDim.x + threadIdx.x) >> 5;
    if (n >= NN) return;
    int q = lane >> 2;        // edge-group 0..7
    int cg = lane & 3;        // uint2 col group: cols 4*cg .. 4*cg+3
    float ad = g_ald[n];
    float a0 = 0.f, a1 = 0.f, a2 = 0.f, a3 = 0.f, den = 0.f;
    const uint2* pu2 = (const uint2*)g_h16v;   // row = 16 halves = 4 uint2
    int beg = g_off[n], end = g_off[n + 1];
    for (int base = beg; base < end; base += 32) {
        int idx = base + lane;
        bool valid = idx < end;
        int s = valid ? g_csr[idx] : 0;
        float ex = valid ? lrelu_exp(__ldg(&g_als[s]) + ad) : 0.f;
        __syncwarp();
        sh_sex[w][lane] = make_float2(__int_as_float(s * 4), ex);
        __syncwarp();
        int nk8 = (min(32, end - base) + 7) & ~7;
        for (int j0 = 0; j0 < nk8; j0 += 8) {
            int j = j0 + q;
            float2 p = sh_sex[w][j];
            int sj4 = __float_as_int(p.x);
            float exj = p.y;
            uint2 v = __ldg(&pu2[sj4 + cg]);
            float2 f0 = __half22float2(*(__half2*)&v.x);
            float2 f1 = __half22float2(*(__half2*)&v.y);
            a0 += exj * f0.x;
            a1 += exj * f0.y;
            a2 += exj * f1.x;
            a3 += exj * f1.y;
            den += exj;
        }
    }
#pragma unroll
    for (int off = 4; off <= 16; off <<= 1) {
        a0 += __shfl_xor_sync(0xffffffffu, a0, off);
        a1 += __shfl_xor_sync(0xffffffffu, a1, off);
        a2 += __shfl_xor_sync(0xffffffffu, a2, off);
        a3 += __shfl_xor_sync(0xffffffffu, a3, off);
        den += __shfl_xor_sync(0xffffffffu, den, off);
    }
    if (lane < 4) {
        float inv = 1.f / (den + 1e-16f);
        float4 o = make_float4(a0 * inv, a1 * inv, a2 * inv, a3 * inv);
        *(float4*)&g_acc[n * 16 + 4 * cg] = o;
    }
}

// ---------------- epilogue layer 3 ----------------
__global__ void ep3(const float* __restrict__ b3, const float* __restrict__ gg,
                    const float* __restrict__ bb, const float* __restrict__ mm,
                    const float* __restrict__ vv, const float* __restrict__ fw1,
                    const float* __restrict__ fb1, const float* __restrict__ fw2,
                    const float* __restrict__ fb2, float* __restrict__ out) {
    int n = blockIdx.x * blockDim.x + threadIdx.x;
    if (n >= NN) return;
    float t[16];
#pragma unroll
    for (int c = 0; c < 16; c++) {
        float y = (g_acc[n * 16 + c] + __ldg(&b3[c]) - __ldg(&mm[c])) *
                      rsqrtf(__ldg(&vv[c]) + 1e-5f) * __ldg(&gg[c]) +
                  __ldg(&bb[c]);
        t[c] = fmaxf(y, 0.f);
    }
    float o = __ldg(&fb2[0]);
#pragma unroll
    for (int oo = 0; oo < 8; oo++) {
        float z = __ldg(&fb1[oo]);
#pragma unroll
        for (int c = 0; c < 16; c++) z += t[c] * __ldg(&fw1[c * 8 + oo]);
        z = fmaxf(z, 0.f);
        o += z * __ldg(&fw2[oo]);
    }
    out[n] = o;
}

// ---------------- launch ----------------
extern "C" void kernel_launch(void* const* d_in, const int* in_sizes, int n_in,
                              void* d_out, int out_size) {
    const float* x = (const float*)d_in[0];
    const int* ei = (const int*)d_in[1];
    const float* W1 = (const float*)d_in[2];
    const float* as1 = (const float*)d_in[3];
    const float* ad1 = (const float*)d_in[4];
    const float* b1 = (const float*)d_in[5];
    const float* g1 = (const float*)d_in[6];
    const float* bb1 = (const float*)d_in[7];
    const float* m1 = (const float*)d_in[8];
    const float* v1 = (const float*)d_in[9];
    const float* W2 = (const float*)d_in[10];
    const float* as2 = (const float*)d_in[11];
    const float* ad2 = (const float*)d_in[12];
    const float* b2 = (const float*)d_in[13];
    const float* g2 = (const float*)d_in[14];
    const float* bb2 = (const float*)d_in[15];
    const float* m2 = (const float*)d_in[16];
    const float* v2 = (const float*)d_in[17];
    const float* W3 = (const float*)d_in[18];
    const float* as3 = (const float*)d_in[19];
    const float* ad3 = (const float*)d_in[20];
    const float* b3 = (const float*)d_in[21];
    const float* g3 = (const float*)d_in[22];
    const float* bb3 = (const float*)d_in[23];
    const float* m3 = (const float*)d_in[24];
    const float* v3 = (const float*)d_in[25];
    const float* fw1 = (const float*)d_in[26];
    const float* fb1 = (const float*)d_in[27];
    const float* fw2 = (const float*)d_in[28];
    const float* fb2 = (const float*)d_in[29];
    float* out = (float*)d_out;

    float* px2 = nullptr;
    cudaGetSymbolAddress((void**)&px2, g_x2);

    const int TB = 256;
    int nblk = (NN + TB - 1) / TB;
    int aggblk = (NN * 32 + TB - 1) / TB;

    // ---- Layer 1 preamble: [full gemm1 || hist+rank] -> scanA -> scanBC -> scatter
    k1_gemm1_hist<<<G64BLK + EBLK, TB>>>(x, W1, as1, ad1, ei);
    scanA<<<NCHK, 256>>>();
    scanBC<<<NCHK, 256>>>();
    scatter_kernel<<<EBLK, TB>>>(ei);
    agg64<<<aggblk, TB>>>(b1, g1, bb1, m1, v1, px2);

    // ---- Layer 2 ----
    gemm64<64><<<G64BLK, TB>>>(px2, W2, as2, ad2);
    agg64<<<aggblk, TB>>>(b2, g2, bb2, m2, v2, px2);

    // ---- Layer 3 ----
    gemm16<<<(NN + 63) / 64, TB>>>(px2, W3, as3, ad3);
    agg16<<<aggblk, TB>>>();
    ep3<<<nblk, TB>>>(b3, g3, bb3, m3, v3, fw1, fb1, fw2, fb2, out);
}